// round 6
// baseline (speedup 1.0000x reference)
#include <cuda_runtime.h>
#include <cstdint>

// ---------------- problem shape ----------------
#define BATCH 32
#define CIN   64
#define HIN   128
#define WIN   128
#define COUT  128
#define HO    126
#define WO    126
#define NGRP  8
#define HP    63
#define WP    63
#define EPS   1e-5f

#define CI_STRIDE 552                 // words per ci: 4 rows * 136 + 8 pad (conflict-free)
#define XS_ELEMS  (16 * CI_STRIDE)    // 8832 words per buffer

// ---------------- scratch (static device globals) ----------------
__device__ float g_pmax[(size_t)BATCH * COUT * HP * WP];
__device__ float g_pmin[(size_t)BATCH * COUT * HP * WP];
__device__ float g_wA[72 * 8 * 32 * 4];
__device__ float g_sum[BATCH * NGRP];
__device__ float g_sumsq[BATCH * NGRP];
__device__ float g_mean[BATCH * NGRP];
__device__ float g_rstd[BATCH * NGRP];

static __device__ __forceinline__ uint32_t f2tf32(float v) {
    uint32_t t;
    asm("cvt.rna.tf32.f32 %0, %1;" : "=r"(t) : "f"(v));
    return t;
}

static __device__ __forceinline__ void mma_tf32(
    float* c, const uint32_t* a, uint32_t b0, uint32_t b1)
{
    asm volatile(
        "mma.sync.aligned.m16n8k8.row.col.f32.tf32.tf32.f32 "
        "{%0,%1,%2,%3}, {%4,%5,%6,%7}, {%8,%9}, {%0,%1,%2,%3};"
        : "+f"(c[0]), "+f"(c[1]), "+f"(c[2]), "+f"(c[3])
        : "r"(a[0]), "r"(a[1]), "r"(a[2]), "r"(a[3]), "r"(b0), "r"(b1));
}

static __device__ __forceinline__ void cp_async16(uint32_t dst_smem, const void* src) {
    asm volatile("cp.async.ca.shared.global [%0], [%1], 16;"
                 :: "r"(dst_smem), "l"(src) : "memory");
}
static __device__ __forceinline__ void cp_commit() {
    asm volatile("cp.async.commit_group;" ::: "memory");
}
template <int N>
static __device__ __forceinline__ void cp_wait() {
    asm volatile("cp.async.wait_group %0;" :: "n"(N) : "memory");
}
static __device__ __forceinline__ uint32_t smem_u32(const void* p) {
    uint32_t a;
    asm("{ .reg .u64 t; cvta.to.shared.u64 t, %1; cvt.u32.u64 %0, t; }"
        : "=r"(a) : "l"(p));
    return a;
}

// ---------------- kernel 0: pack W + zero sums ----------------
__global__ __launch_bounds__(256)
void pack_kernel(const float* __restrict__ W)
{
    int idx = blockIdx.x * 256 + threadIdx.x;        // 73728 total
    if (idx < BATCH * NGRP) { g_sum[idx] = 0.f; g_sumsq[idx] = 0.f; }
    if (idx >= 72 * 8 * 32 * 4) return;
    int j      = idx & 3;
    int lane   = (idx >> 2) & 31;
    int mt     = (idx >> 7) & 7;
    int kchunk = idx >> 10;
    int cg  = kchunk / 18;
    int t2  = kchunk % 18;
    int tap = t2 >> 1;
    int ci8 = t2 & 1;
    int kk = (lane & 3) + ((j >= 2) ? 4 : 0);
    int r  = (lane >> 2) + ((j & 1) ? 8 : 0);
    int cout = mt * 16 + r;
    int ci   = cg * 16 + ci8 * 8 + kk;
    int kh = tap / 3, kw = tap % 3;
    float v = W[((cout * CIN + ci) * 3 + kh) * 3 + kw];
    ((uint32_t*)g_wA)[idx] = f2tf32(v);
}

// ---------------- kernel 1: conv + bias + GN partials + fused 2x2 max/min ----
// Grid: (63, 32). CTA: 128 couts x (2 rows x 128 cols). 8 warps 2M x 4N.
// Warp n-tiles: nt 0..3 -> row0 cols nt*8, nt 4..7 -> row1 cols nt*8.
__global__ __launch_bounds__(256, 1)
void conv_mma_kernel(const float* __restrict__ x,
                     const float* __restrict__ bias)
{
    extern __shared__ uint32_t xs[];   // [2][XS_ELEMS] raw f32 bits
    const uint32_t xs_base = smem_u32(xs);

    const int tid  = threadIdx.x;
    const int wid  = tid >> 5;
    const int lane = tid & 31;
    const int warp_m = wid >> 2;            // 0..1
    const int warp_n = wid & 3;             // 0..3
    const int rg = blockIdx.x;              // pooled row
    const int b  = blockIdx.y;
    const int ho0 = rg * 2;

    // zero pad cols 128..135 (2 float4 per (buf,ci,row))
    {
        int i = tid;                                   // 256 = 2*16*4*2 exactly
        int buf = i & 1;
        int row = (i >> 1) & 3;
        int ci  = i >> 3;                              // 0..31 -> buf? no: 2*16*4=128... 
        // careful: total slots = 2 buf *16 ci *4 row *2 q = 256
        int q = buf; (void)q;
        int t = tid;
        int qq  = t & 1;
        int rr  = (t >> 1) & 3;
        int cci = (t >> 3) & 15;
        int bbf = t >> 7;
        float4* p = reinterpret_cast<float4*>(xs + bbf * XS_ELEMS + cci * CI_STRIDE + rr * 136 + 128 + qq * 4);
        *p = make_float4(0.f, 0.f, 0.f, 0.f);
        (void)i; (void)buf; (void)row; (void)ci;
    }
    __syncthreads();

    // stage: 16 ci x 4 rows x 32 float4 = 2048 float4, 8 per thread
    auto stage = [&](int cg) {
        const uint32_t dstb = xs_base + (cg & 1) * (XS_ELEMS * 4);
        const float* src_base = x + (((size_t)b * CIN + cg * 16) * HIN + ho0) * WIN;
#pragma unroll
        for (int k = 0; k < 8; k++) {
            int c = tid + 256 * k;          // 0..2047
            int ci  = c >> 7;
            int rem = c & 127;
            int rr  = rem >> 5;
            int q   = rem & 31;
            cp_async16(dstb + (uint32_t)(ci * CI_STRIDE + rr * 136 + q * 4) * 4,
                       src_base + (size_t)ci * (HIN * WIN) + rr * WIN + q * 4);
        }
        cp_commit();
    };

    float acc[4][8][4];
#pragma unroll
    for (int i = 0; i < 4; i++)
#pragma unroll
        for (int n = 0; n < 8; n++)
#pragma unroll
            for (int k = 0; k < 4; k++) acc[i][n][k] = 0.f;

    const int lq = lane & 3;    // k index / col pair
    const int lr = lane >> 2;   // m row / col offset

    stage(0);

    for (int cg = 0; cg < 4; cg++) {
        if (cg + 1 < 4) stage(cg + 1);
        if (cg + 1 < 4) cp_wait<1>(); else cp_wait<0>();
        __syncthreads();

        const uint32_t* xbuf = xs + (cg & 1) * XS_ELEMS;
        const uint32_t* xrow0 = xbuf + (lq)     * CI_STRIDE;   // + ci8*8*CI_STRIDE
        const uint32_t* xrow1 = xbuf + (lq + 4) * CI_STRIDE;

#pragma unroll
        for (int tap = 0; tap < 9; tap++) {
            const int kh = tap / 3, kw = tap % 3;
#pragma unroll
            for (int ci8 = 0; ci8 < 2; ci8++) {
                const int kchunk = cg * 18 + tap * 2 + ci8;
                uint32_t a[4][4];
#pragma unroll
                for (int i = 0; i < 4; i++) {
                    float4 f = __ldg(&reinterpret_cast<const float4*>(g_wA)[
                        (kchunk * 8 + warp_m * 4 + i) * 32 + lane]);
                    a[i][0] = __float_as_uint(f.x);
                    a[i][1] = __float_as_uint(f.y);
                    a[i][2] = __float_as_uint(f.z);
                    a[i][3] = __float_as_uint(f.w);
                }
                uint32_t b0[8], b1[8];
                const int cb = warp_n * 32 + lr + kw;
                const uint32_t* r0 = xrow0 + ci8 * 8 * CI_STRIDE + kh * 136;
                const uint32_t* r1 = xrow1 + ci8 * 8 * CI_STRIDE + kh * 136;
#pragma unroll
                for (int nt = 0; nt < 8; nt++) {
                    const int addr = ((nt >> 2)) * 136 + cb + (nt & 3) * 8;
                    b0[nt] = r0[addr];
                    b1[nt] = r1[addr];
                }
#pragma unroll
                for (int i = 0; i < 4; i++)
#pragma unroll
                    for (int nt = 0; nt < 8; nt++)
                        mma_tf32(acc[i][nt], a[i], b0[nt], b1[nt]);
            }
        }
        __syncthreads();
    }

    // ---- epilogue: bias, GN partials, fused 2x2 max/min, store pooled ----
    float sacc[4], qacc[4];
#pragma unroll
    for (int i = 0; i < 4; i++) { sacc[i] = 0.f; qacc[i] = 0.f; }

#pragma unroll
    for (int i = 0; i < 4; i++) {
        const int c0 = warp_m * 64 + i * 16 + lr;
        const int c1 = c0 + 8;
        const float bv0 = bias[c0];
        const float bv1 = bias[c1];
        float* pmax0 = g_pmax + (((size_t)b * COUT + c0) * HP + rg) * WP;
        float* pmin0 = g_pmin + (((size_t)b * COUT + c0) * HP + rg) * WP;
        float* pmax1 = g_pmax + (((size_t)b * COUT + c1) * HP + rg) * WP;
        float* pmin1 = g_pmin + (((size_t)b * COUT + c1) * HP + rg) * WP;
#pragma unroll
        for (int nt = 0; nt < 4; nt++) {
            const int col = warp_n * 32 + nt * 8 + 2 * lq;
            if (col < WO) {
                // row0 values (nt), row1 values (nt+4); c-regs: [0]=col,c0 [1]=col+1,c0 [2]=col,c1 [3]=col+1,c1
                float a00 = acc[i][nt][0] + bv0,   a01 = acc[i][nt][1] + bv0;
                float a10 = acc[i][nt+4][0] + bv0, a11 = acc[i][nt+4][1] + bv0;
                float d00 = acc[i][nt][2] + bv1,   d01 = acc[i][nt][3] + bv1;
                float d10 = acc[i][nt+4][2] + bv1, d11 = acc[i][nt+4][3] + bv1;

                sacc[i] += (a00 + a01 + a10 + a11) + (d00 + d01 + d10 + d11);
                qacc[i] += a00*a00 + a01*a01 + a10*a10 + a11*a11
                         + d00*d00 + d01*d01 + d10*d10 + d11*d11;

                const int wp = (col >> 1);
                pmax0[wp] = fmaxf(fmaxf(a00, a01), fmaxf(a10, a11));
                pmin0[wp] = fminf(fminf(a00, a01), fminf(a10, a11));
                pmax1[wp] = fmaxf(fmaxf(d00, d01), fmaxf(d10, d11));
                pmin1[wp] = fminf(fminf(d00, d01), fminf(d10, d11));
            }
        }
    }
#pragma unroll
    for (int i = 0; i < 4; i++) {
        float s = sacc[i], q = qacc[i];
#pragma unroll
        for (int off = 16; off > 0; off >>= 1) {
            s += __shfl_xor_sync(0xFFFFFFFF, s, off);
            q += __shfl_xor_sync(0xFFFFFFFF, q, off);
        }
        if (lane == 0) {
            const int g = warp_m * 4 + i;
            atomicAdd(&g_sum[b * NGRP + g], s);
            atomicAdd(&g_sumsq[b * NGRP + g], q);
        }
    }
}

// ---------------- kernel 2: finalize stats ----------------
__global__ void stats_final_kernel()
{
    int t = threadIdx.x;
    if (t < BATCH * NGRP) {
        const float n = (float)((COUT / NGRP) * HO * WO);
        float m = g_sum[t] / n;
        float var = g_sumsq[t] / n - m * m;
        g_mean[t] = m;
        g_rstd[t] = rsqrtf(var + EPS);
    }
}

// ---------------- kernel 3: elementwise normalize+clamp on pooled max/min ----
__global__ __launch_bounds__(256)
void final_kernel(const float* __restrict__ scale,
                  const float* __restrict__ gamma,
                  const float* __restrict__ beta,
                  float* __restrict__ out,
                  int total)
{
    int idx = blockIdx.x * 256 + threadIdx.x;
    if (idx >= total) return;

    int t = idx / (HP * WP);
    int c = t % COUT;
    int b = t / COUT;
    int g = c / (COUT / NGRP);

    const float mean = g_mean[b * NGRP + g];
    const float rstd = g_rstd[b * NGRP + g];
    const float a  = rstd * gamma[c] * scale[c];
    const float bb = (beta[c] - mean * rstd * gamma[c]) * scale[c];

    float v = (a >= 0.f) ? __ldcs(&g_pmax[idx]) : __ldcs(&g_pmin[idx]);
    float m = a * v + bb;
    m = fminf(fmaxf(m, 0.0f), 1.0f);
    out[idx] = m;
}

// ---------------- host launcher ----------------
extern "C" void kernel_launch(void* const* d_in, const int* in_sizes, int n_in,
                              void* d_out, int out_size)
{
    const float* x     = (const float*)d_in[0];
    const float* W     = (const float*)d_in[1];
    const float* bias  = (const float*)d_in[2];
    const float* scale = (const float*)d_in[3];
    const float* gamma = (const float*)d_in[4];
    const float* beta  = (const float*)d_in[5];
    float* out = (float*)d_out;

    static int smem_set = 0;
    const int smem_bytes = 2 * XS_ELEMS * 4;   // 70656
    if (!smem_set) {
        cudaFuncSetAttribute(conv_mma_kernel,
                             cudaFuncAttributeMaxDynamicSharedMemorySize, smem_bytes);
        smem_set = 1;
    }

    pack_kernel<<<288, 256>>>(W);

    dim3 cgrid(HP, BATCH);       // 63 x 32
    conv_mma_kernel<<<cgrid, 256, smem_bytes>>>(x, bias);

    stats_final_kernel<<<1, 256>>>();

    const int total = BATCH * COUT * HP * WP;
    final_kernel<<<(total + 255) / 256, 256>>>(scale, gamma, beta, out, total);
}